// round 9
// baseline (speedup 1.0000x reference)
#include <cuda_runtime.h>

// Exact L-inf nearest neighbor. 5 graph-captured kernels:
//   count_k   : multi-block, atomicAdd into g_cnt (also zeroes fail counter).
//   scan_k    : ONE block, register scan of 9216 counts -> CSR offsets g_off.
//   scatter_k : multi-block; pos via atomicSub(g_cnt) -> g_cnt ends ALL-ZERO,
//               restoring the cross-replay invariant (globals are zero-init).
//   fast_k    : 4 lanes/query; rings 0+1 = 3 contiguous CSR row spans, points
//               spread over lanes with a software-pipelined (prefetch) loop,
//               u64 pack+min, 2-level shfl reduce, geometric wall-bound
//               accept; failures pushed to a list.
//   slow_k    : one FULL WARP per failed query; exact expanding Chebyshev
//               rings over the CSR with per-ring wall bounds.
// u64 pack (dist_bits<<32 | idx<<14 | pos), payload PRECOMPUTED at scatter
// into pt.z: min() IS the lexicographic (d, idx) compare -> exact
// jnp.argmin first-index tie semantics. Wall-bound soundness: out-of-range B
// points are clamped into edge cells, so when the covered rect touches a
// grid edge that wall is dropped; all unscanned points are beyond a
// remaining wall, and strict inequality (EPS) forbids cross-wall ties.

#define G      96
#define NCELL  (G * G)                   // 9216
#define X0     (-4.5f)
#define EXT    9.0f
#define H      (EXT / (float)G)          // 0.09375, binary exact
#define INVH   ((float)G / EXT)
#define MAXPTS 16384
#define EPS    1e-6f
#define CPT    (NCELL / 1024)            // cells per thread in scan_k = 9

__device__ int    g_cnt[NCELL];          // counts; returns to zero each run
__device__ int    g_off[NCELL + 1];      // CSR offsets
__device__ float4 g_pts[MAXPTS];         // (x, y, payload_bits, 0)
__device__ int    g_fail_cnt;
__device__ int    g_fail[32768];

__device__ __forceinline__ int cell_coord(float v) {
    int c = __float2int_rd((v - X0) * INVH);
    return min(max(c, 0), G - 1);
}

// ---------------- build stage 1: count ----------------
__global__ void __launch_bounds__(256)
count_k(const float* __restrict__ B, int N)
{
    int n = blockIdx.x * 256 + threadIdx.x;
    if (n == 0) g_fail_cnt = 0;
    if (n >= N) return;
    int c = cell_coord(B[N + n]) * G + cell_coord(B[n]);
    atomicAdd(&g_cnt[c], 1);
}

// ---------------- build stage 2: scan (one block, registers only) ----------
__global__ void __launch_bounds__(1024)
scan_k()
{
    __shared__ int s_wsum[32];
    const int t = threadIdx.x;
    const int base = t * CPT;

    int local[CPT]; int tot = 0;
    #pragma unroll
    for (int i = 0; i < CPT; ++i) { local[i] = g_cnt[base + i]; tot += local[i]; }

    const int lane = t & 31, wid = t >> 5;
    int v = tot;
    #pragma unroll
    for (int m = 1; m < 32; m <<= 1) {
        int u = __shfl_up_sync(0xffffffffu, v, m);
        if (lane >= m) v += u;
    }
    if (lane == 31) s_wsum[wid] = v;
    __syncthreads();
    if (wid == 0) {
        int w = s_wsum[lane];
        #pragma unroll
        for (int m = 1; m < 32; m <<= 1) {
            int u = __shfl_up_sync(0xffffffffu, w, m);
            if (lane >= m) w += u;
        }
        s_wsum[lane] = w;
    }
    __syncthreads();

    int excl = v - tot + (wid ? s_wsum[wid - 1] : 0);
    #pragma unroll
    for (int i = 0; i < CPT; ++i) { g_off[base + i] = excl; excl += local[i]; }
    if (t == 1023) g_off[NCELL] = excl;
}

// ---------------- build stage 3: scatter (self-zeroing counters) ----------
__global__ void __launch_bounds__(256)
scatter_k(const float* __restrict__ B, int N)
{
    int n = blockIdx.x * 256 + threadIdx.x;
    if (n >= N) return;
    float x = B[n], y = B[N + n];
    int c = cell_coord(y) * G + cell_coord(x);
    int rank = atomicSub(&g_cnt[c], 1) - 1;      // g_cnt ends at 0 -> reusable
    int pos  = g_off[c] + rank;
    unsigned pay = ((unsigned)n << 14) | (unsigned)pos;
    g_pts[pos] = make_float4(x, y, __uint_as_float(pay), 0.0f);
}

// ---------------- query helpers ----------------
__device__ __forceinline__ unsigned long long
eval_pt(float4 pt, float ax, float ay)
{
    float d = fmaxf(fabsf(ax - pt.x), fabsf(ay - pt.y));
    return (((unsigned long long)__float_as_uint(d)) << 32)
           | (unsigned long long)__float_as_uint(pt.z);
}

// ---------------- fast kernel: 4 lanes/query ----------------
__global__ void __launch_bounds__(256, 8)
fast_k(const float* __restrict__ A, float* __restrict__ out, int Q)
{
    const int tid  = blockIdx.x * 256 + threadIdx.x;
    const int q    = tid >> 2;
    const int lane = tid & 3;
    if (q >= Q) return;

    const unsigned gmask = 0xFu << (threadIdx.x & 28);

    const float2 aq = __ldg(&((const float2*)A)[q]);
    const float ax = aq.x, ay = aq.y;
    const int cx = cell_coord(ax);
    const int cy = cell_coord(ay);

    const int i0  = max(cx - 1, 0);
    const int i1p = min(cx + 1, G - 1) + 1;

    int s0 = 0, c0 = 0, s1, c1, s2 = 0, c2 = 0;
    if (cy - 1 >= 0) {
        int rb = (cy - 1) * G;
        s0 = __ldg(&g_off[rb + i0]); c0 = __ldg(&g_off[rb + i1p]) - s0;
    }
    {
        int rb = cy * G;
        s1 = __ldg(&g_off[rb + i0]); c1 = __ldg(&g_off[rb + i1p]) - s1;
    }
    if (cy + 1 <= G - 1) {
        int rb = (cy + 1) * G;
        s2 = __ldg(&g_off[rb + i0]); c2 = __ldg(&g_off[rb + i1p]) - s2;
    }

    const int c01 = c0 + c1;
    const int T   = c01 + c2;

    unsigned long long best = 0xFFFFFFFFFFFFFFFFull;

    // software-pipelined scan: prefetch next point before consuming current
    int k = lane;
    if (k < T) {
        int p = (k < c0) ? (s0 + k) : ((k < c01) ? (s1 + k - c0) : (s2 + k - c01));
        float4 pt = __ldg(&g_pts[p]);
        for (;;) {
            int kn = k + 4;
            bool more = kn < T;
            float4 ptn;
            if (more) {
                int pn = (kn < c0) ? (s0 + kn)
                                   : ((kn < c01) ? (s1 + kn - c0) : (s2 + kn - c01));
                ptn = __ldg(&g_pts[pn]);
            }
            best = min(best, eval_pt(pt, ax, ay));
            if (!more) break;
            pt = ptn; k = kn;
        }
    }
    best = min(best, __shfl_xor_sync(gmask, best, 2));
    best = min(best, __shfl_xor_sync(gmask, best, 1));

    if (lane == 0) {
        // wall bound of covered rect = cells [cx-1,cx+1] x [cy-1,cy+1]
        float mb = __int_as_float(0x7f800000);
        if (cx - 1 > 0)     mb = fminf(mb, ax - (X0 + (float)(cx - 1) * H));
        if (cx + 1 < G - 1) mb = fminf(mb, (X0 + (float)(cx + 2) * H) - ax);
        if (cy - 1 > 0)     mb = fminf(mb, ay - (X0 + (float)(cy - 1) * H));
        if (cy + 1 < G - 1) mb = fminf(mb, (X0 + (float)(cy + 2) * H) - ay);

        float bd = __uint_as_float((unsigned)(best >> 32));
        if (bd <= mb - EPS) {
            float4 pt = __ldg(&g_pts[(unsigned)best & 0x3FFFu]);
            ((float2*)out)[q] = make_float2(ax - pt.x, ay - pt.y);
        } else {
            int slot = atomicAdd(&g_fail_cnt, 1);
            g_fail[slot] = q;
        }
    }
}

// ---------------- slow kernel: one warp per failed query ----------------
__global__ void __launch_bounds__(256)
slow_k(const float* __restrict__ A, float* __restrict__ out, int nwarps_total)
{
    const int wglob = blockIdx.x * 8 + (threadIdx.x >> 5);
    const int lane  = threadIdx.x & 31;
    const int cnt   = g_fail_cnt;

    for (int f = wglob; f < cnt; f += nwarps_total) {
        const int q = g_fail[f];
        const float2 aq = __ldg(&((const float2*)A)[q]);
        const float ax = aq.x, ay = aq.y;
        const int cx = cell_coord(ax);
        const int cy = cell_coord(ay);

        unsigned long long best = 0xFFFFFFFFFFFFFFFFull;
        for (int r = 0; ; ++r) {
            if (r == 0) {
                if (lane == 0) {
                    int c = cy * G + cx;
                    int s = __ldg(&g_off[c]), e = __ldg(&g_off[c + 1]);
                    for (int p = s; p < e; ++p)
                        best = min(best, eval_pt(__ldg(&g_pts[p]), ax, ay));
                }
            } else {
                int nc = 8 * r;
                for (int tc = lane; tc < nc; tc += 32) {
                    int i, j;
                    if (tc < 2 * r + 1)      { i = cx - r + tc;               j = cy - r; }
                    else if (tc < 4 * r + 2) { i = cx - r + (tc - (2*r + 1)); j = cy + r; }
                    else { int s = tc - (4*r + 2); j = cy - r + 1 + (s >> 1);
                           i = (s & 1) ? cx + r : cx - r; }
                    if ((unsigned)i < G && (unsigned)j < G) {
                        int c = j * G + i;
                        int s = __ldg(&g_off[c]), e = __ldg(&g_off[c + 1]);
                        for (int p = s; p < e; ++p)
                            best = min(best, eval_pt(__ldg(&g_pts[p]), ax, ay));
                    }
                }
            }
            #pragma unroll
            for (int m = 16; m >= 1; m >>= 1)
                best = min(best, __shfl_xor_sync(0xffffffffu, best, m));

            if (cx - r <= 0 && cx + r >= G - 1 &&
                cy - r <= 0 && cy + r >= G - 1) break;
            float mb = __int_as_float(0x7f800000);
            if (cx - r > 0)     mb = fminf(mb, ax - (X0 + (float)(cx - r) * H));
            if (cx + r < G - 1) mb = fminf(mb, (X0 + (float)(cx + r + 1) * H) - ax);
            if (cy - r > 0)     mb = fminf(mb, ay - (X0 + (float)(cy - r) * H));
            if (cy + r < G - 1) mb = fminf(mb, (X0 + (float)(cy + r + 1) * H) - ay);
            float bd = __uint_as_float((unsigned)(best >> 32));
            if (bd <= mb - EPS) break;
        }

        if (lane == 0) {
            float4 pt = __ldg(&g_pts[(unsigned)best & 0x3FFFu]);
            ((float2*)out)[q] = make_float2(ax - pt.x, ay - pt.y);
        }
    }
}

extern "C" void kernel_launch(void* const* d_in, const int* in_sizes, int n_in,
                              void* d_out, int out_size)
{
    const float* A = (const float*)d_in[0];   // [Q, 2]
    const float* B = (const float*)d_in[1];   // [2, N]
    float*     out = (float*)d_out;           // [Q, 2]

    const int Q = in_sizes[0] / 2;
    const int N = in_sizes[1] / 2;

    count_k  <<<(N + 255) / 256, 256>>>(B, N);
    scan_k   <<<1, 1024>>>();
    scatter_k<<<(N + 255) / 256, 256>>>(B, N);

    fast_k<<<(Q * 4 + 255) / 256, 256>>>(A, out, Q);

    const int slow_blocks = 256;
    slow_k<<<slow_blocks, 256>>>(A, out, slow_blocks * 8);
}